// round 14
// baseline (speedup 1.0000x reference)
#include <cuda_runtime.h>
#include <math.h>
#include <float.h>

#define DDEPTH 7
#define IND   128
#define GRIDN 128
#define HIDN  256
#define BATCHN 2048
#define NT    129          // t in 0..128
#define TROW  512          // floats per (d,i) across all h

// k_main tiling
#define MAIN_TPB 512
#define BCB   1024         // batches per CTA
#define IPC   16           // i's per CTA
#define NIC   8            // i-chunk count (128/IPC)
#define CHUNKF 64          // floats per t-row within one 32-h chunk
#define SLICE_F4 (NT * 16)              // 2064 float4 per slice
#define SLICE_BYTES (NT * CHUNKF * 4)   // 33024
#define BUF_F4 (2 * SLICE_F4)           // fused double-slice buffer
#define SMEM_MAIN (2 * BUF_F4 * 16 + IPC * BCB * 4 + 64)   // 197696

// ---------------- scratch (static device memory; no allocation) ----------------
__device__ float g_xmin[IND];
__device__ float g_xmax[IND];
__device__ float g_Zt[IND * BATCHN];             // z transposed: [i][b]
// layout: [d][i][hc8][t][64 floats]  (c_d folded in)
__device__ float g_T[(size_t)DDEPTH * IND * NT * TROW];
__device__ unsigned char g_tmap[(size_t)DDEPTH * IND * BATCHN];
__device__ float g_Hp[(size_t)NIC * BATCHN * HIDN];       // i-split partials
__device__ float g_Ha[BATCHN * HIDN];
__device__ float g_Hb[BATCHN * HIDN];
__device__ double g_sum[HIDN];
__device__ double g_sumsq[HIDN];
__device__ float2 g_bnp[HIDN];

// ---------------- mbarrier + bulk-copy helpers ----------------
__device__ __forceinline__ unsigned int smem_u32(const void* p) {
    return (unsigned int)__cvta_generic_to_shared(p);
}
__device__ __forceinline__ void mbar_init(unsigned int a, unsigned int cnt) {
    asm volatile("mbarrier.init.shared.b64 [%0], %1;" :: "r"(a), "r"(cnt) : "memory");
}
__device__ __forceinline__ void mbar_expect(unsigned int a, unsigned int tx) {
    asm volatile("mbarrier.arrive.expect_tx.shared.b64 _, [%0], %1;" :: "r"(a), "r"(tx) : "memory");
}
__device__ __forceinline__ void mbar_arrive(unsigned int a) {
    asm volatile("mbarrier.arrive.release.cta.shared.b64 _, [%0];" :: "r"(a) : "memory");
}
__device__ __forceinline__ void bulk_g2s(unsigned int dst, const void* src,
                                         unsigned int bytes, unsigned int mbar) {
    asm volatile("cp.async.bulk.shared::cta.global.mbarrier::complete_tx::bytes [%0], [%1], %2, [%3];"
                 :: "r"(dst), "l"(src), "r"(bytes), "r"(mbar) : "memory");
}
__device__ __forceinline__ void mbar_wait(unsigned int a, unsigned int parity) {
    asm volatile(
        "{\n\t"
        ".reg .pred P;\n\t"
        "W_%=:\n\t"
        "mbarrier.try_wait.parity.acquire.cta.shared::cta.b64 P, [%0], %1;\n\t"
        "@P bra D_%=;\n\t"
        "bra W_%=;\n\t"
        "D_%=:\n\t"
        "}"
        :: "r"(a), "r"(parity) : "memory");
}

// ---------------- 1. fused: per-feature min/max + z + stats zero ----------------
// grid = IND, 256 threads. CTA i reduces over batch, writes g_Zt[i][*].
__global__ void __launch_bounds__(256) k_prep1(const float* __restrict__ x) {
    int i = blockIdx.x;
    float mn = FLT_MAX, mx = -FLT_MAX;
    for (int b = threadIdx.x; b < BATCHN; b += 256) {
        float v = x[b * IND + i];
        mn = fminf(mn, v);
        mx = fmaxf(mx, v);
    }
    __shared__ float smn[256], smx[256];
    smn[threadIdx.x] = mn; smx[threadIdx.x] = mx;
    __syncthreads();
    for (int s = 128; s > 0; s >>= 1) {
        if (threadIdx.x < s) {
            smn[threadIdx.x] = fminf(smn[threadIdx.x], smn[threadIdx.x + s]);
            smx[threadIdx.x] = fmaxf(smx[threadIdx.x], smx[threadIdx.x + s]);
        }
        __syncthreads();
    }
    float lo = smn[0];
    float inv = 1.0f / (smx[0] - lo + 1e-6f);
    for (int b = threadIdx.x; b < BATCHN; b += 256)
        g_Zt[i * BATCHN + b] = (x[b * IND + i] - lo) * inv;
    if (blockIdx.x == 0) { g_sum[threadIdx.x] = 0.0; g_sumsq[threadIdx.x] = 0.0; }
}

// ---------------- 2. fused: sort + prefix table (c_d folded) + tmap ----------------
// grid = DDEPTH*IND, 128 threads. Sorted grids live only in smem.
__global__ void __launch_bounds__(128) k_prep2(const float* __restrict__ grids,
                                               const float* __restrict__ fs,
                                               const float* __restrict__ ds) {
    __shared__ float raw[GRIDN];
    __shared__ float ssg[GRIDN];
    __shared__ int   spm[GRIDN];
    int di = blockIdx.x;
    int d  = di >> 7;
    int t  = threadIdx.x;               // 0..127

    // --- sort by rank (stable) ---
    float g = grids[di * GRIDN + t];
    raw[t] = g;
    __syncthreads();
    int r = 0;
    #pragma unroll 8
    for (int j = 0; j < GRIDN; j++) {
        float gj = raw[j];
        r += (gj < g) || (gj == g && j < t);
    }
    ssg[r] = g;
    spm[r] = t;

    // depth suffix-softmax weight c_d (redundant per thread, tiny)
    float w[DDEPTH], m = -FLT_MAX;
    for (int k = 0; k < DDEPTH; k++) m = fmaxf(m, ds[k]);
    float ssum = 0.f;
    for (int k = 0; k < DDEPTH; k++) { w[k] = expf(ds[k] - m); ssum += w[k]; }
    float cd = 0.f;
    for (int k = DDEPTH - 1; k >= d; --k) cd += w[k] / ssum;
    __syncthreads();

    // --- prefix tables: thread owns h pair (2t, 2t+1) ---
    int h2 = t;
    const float* fbase = fs + (size_t)di * GRIDN * HIDN + 2 * h2;
    float* base = g_T + (size_t)di * NT * TROW + (h2 >> 4) * (NT * CHUNKF) + (h2 & 15) * 4;
    float a10 = 0.f, a20 = 0.f, a11 = 0.f, a21 = 0.f;
    *(float4*)base = make_float4(0.f, 0.f, 0.f, 0.f);
    for (int t0 = 0; t0 < GRIDN; t0 += 4) {
        int p0 = spm[t0 + 0], p1 = spm[t0 + 1], p2 = spm[t0 + 2], p3 = spm[t0 + 3];
        float2 f0 = *(const float2*)(fbase + p0 * HIDN);
        float2 f1 = *(const float2*)(fbase + p1 * HIDN);
        float2 f2 = *(const float2*)(fbase + p2 * HIDN);
        float2 f3 = *(const float2*)(fbase + p3 * HIDN);
        float g0 = ssg[t0 + 0], g1 = ssg[t0 + 1], g2 = ssg[t0 + 2], g3 = ssg[t0 + 3];
        a10 += f0.x; a20 = fmaf(g0, f0.x, a20);
        a11 += f0.y; a21 = fmaf(g0, f0.y, a21);
        *(float4*)(base + (size_t)(t0 + 1) * CHUNKF) = make_float4(cd*a10, cd*a20, cd*a11, cd*a21);
        a10 += f1.x; a20 = fmaf(g1, f1.x, a20);
        a11 += f1.y; a21 = fmaf(g1, f1.y, a21);
        *(float4*)(base + (size_t)(t0 + 2) * CHUNKF) = make_float4(cd*a10, cd*a20, cd*a11, cd*a21);
        a10 += f2.x; a20 = fmaf(g2, f2.x, a20);
        a11 += f2.y; a21 = fmaf(g2, f2.y, a21);
        *(float4*)(base + (size_t)(t0 + 3) * CHUNKF) = make_float4(cd*a10, cd*a20, cd*a11, cd*a21);
        a10 += f3.x; a20 = fmaf(g3, f3.x, a20);
        a11 += f3.y; a21 = fmaf(g3, f3.y, a21);
        *(float4*)(base + (size_t)(t0 + 4) * CHUNKF) = make_float4(cd*a10, cd*a20, cd*a11, cd*a21);
    }

    // --- tmap: t[d,i,b] = #{ g < z } via binary search in ssg ---
    int i = di & (IND - 1);
    for (int b = t; b < BATCHN; b += 128) {
        float z = g_Zt[i * BATCHN + b];
        int tt = 0;
        #pragma unroll
        for (int s = 64; s > 0; s >>= 1) {
            int nt = tt + s;
            if (nt <= GRIDN && ssg[nt - 1] < z) tt = nt;
        }
        g_tmap[(size_t)di * BATCHN + b] = (unsigned char)tt;
    }
}

// ---------------- 3. main kernel: fused double-slice steps, mbarrier ring ----------------
// grid = 128: bc = x&1 (1024 b), hc = (x>>1)&7 (32 h), ic = x>>4 (8 chunks of 16 i).
// 512 threads (16 warps): hp = tid&15 (h-pair in chunk), bg = tid>>4 (32 batches each).
// Step s = il*4 + g covers d-group {2g, 2g+1} (g<3) or {6} (g==3): 64 steps.
// Buffer holds 2 slices (66KB). Ring: full cnt 1 + expect_tx, empty cnt 16.
__global__ void __launch_bounds__(MAIN_TPB, 1) k_main() {
    extern __shared__ float4 dynsmem[];
    float4* bufs = dynsmem;                               // [2][BUF_F4]
    float*  z_s  = (float*)(dynsmem + 2 * BUF_F4);        // [IPC][BCB] 64KB
    unsigned long long* mbar = (unsigned long long*)(z_s + IPC * BCB);  // fb0,fb1,eb0,eb1

    int bc = blockIdx.x & 1;
    int hc = (blockIdx.x >> 1) & 7;
    int ic = blockIdx.x >> 4;
    int tid = threadIdx.x;
    int hp = tid & 15;
    int bg = tid >> 4;          // 0..31
    int b0 = bc * BCB;
    int i0 = ic * IPC;

    unsigned int fb0 = smem_u32(&mbar[0]);
    unsigned int fb1 = smem_u32(&mbar[1]);
    unsigned int eb0 = smem_u32(&mbar[2]);
    unsigned int eb1 = smem_u32(&mbar[3]);
    unsigned int rb0 = smem_u32(&bufs[0]);
    unsigned int rb1 = smem_u32(&bufs[BUF_F4]);

    if (tid == 0) {
        mbar_init(fb0, 1);  mbar_init(fb1, 1);
        mbar_init(eb0, 16); mbar_init(eb1, 16);
    }

    for (int idx = tid; idx < IPC * BCB; idx += MAIN_TPB) {
        int il = idx >> 10, bl = idx & (BCB - 1);
        z_s[idx] = g_Zt[(i0 + il) * BATCHN + b0 + bl];
    }
    __syncthreads();   // mbar init + z_s visible

    const int NS = IPC * 4;   // 64 fused steps
    // stage fused step s into buffer addr `dst` with barrier fb
    auto stage = [&](int s, unsigned int dst, unsigned int fb) {
        int il = s >> 2, gq = s & 3;
        int d0 = 2 * gq;
        int nd = (gq < 3) ? 2 : 1;
        mbar_expect(fb, nd * SLICE_BYTES);
        const float* src0 = g_T + (size_t)(d0 * IND + i0 + il) * (NT * TROW)
                                + (size_t)hc * (NT * CHUNKF);
        bulk_g2s(dst, src0, SLICE_BYTES, fb);
        if (nd == 2) {
            const float* src1 = src0 + (size_t)IND * (NT * TROW);
            bulk_g2s(dst + SLICE_BYTES, src1, SLICE_BYTES, fb);
        }
    };

    if (tid == 0) { stage(0, rb0, fb0); stage(1, rb1, fb1); }

    float2 acc[32];
    #pragma unroll
    for (int j = 0; j < 32; j++) acc[j] = make_float2(0.f, 0.f);

    for (int s = 0; s < NS; s++) {
        int il = s >> 2, gq = s & 3;
        int d0 = 2 * gq;
        int nd = (gq < 3) ? 2 : 1;

        unsigned int par = (s >> 1) & 1;
        mbar_wait((s & 1) ? fb1 : fb0, par);

        // z for this il (shared across both d's of the fused step)
        const float4* zp = (const float4*)(z_s + il * BCB + bg * 32);
        float4 zq0 = zp[0], zq1 = zp[1], zq2 = zp[2], zq3 = zp[3];
        float4 zq4 = zp[4], zq5 = zp[5], zq6 = zp[6], zq7 = zp[7];

        const float4* bbase = bufs + (size_t)(s & 1) * BUF_F4;

        #define STEP4(W, Z4, JA) { \
            unsigned int w_ = (W); \
            float4 z4 = (Z4); \
            float4 v0 = rb[(w_ & 255u) * 16 + hp]; \
            float4 v1 = rb[((w_ >> 8) & 255u) * 16 + hp]; \
            float4 v2 = rb[((w_ >> 16) & 255u) * 16 + hp]; \
            float4 v3 = rb[(w_ >> 24) * 16 + hp]; \
            acc[JA+0].x = fmaf(z4.x, v0.x, acc[JA+0].x - v0.y); \
            acc[JA+0].y = fmaf(z4.x, v0.z, acc[JA+0].y - v0.w); \
            acc[JA+1].x = fmaf(z4.y, v1.x, acc[JA+1].x - v1.y); \
            acc[JA+1].y = fmaf(z4.y, v1.z, acc[JA+1].y - v1.w); \
            acc[JA+2].x = fmaf(z4.z, v2.x, acc[JA+2].x - v2.y); \
            acc[JA+2].y = fmaf(z4.z, v2.z, acc[JA+2].y - v2.w); \
            acc[JA+3].x = fmaf(z4.w, v3.x, acc[JA+3].x - v3.y); \
            acc[JA+3].y = fmaf(z4.w, v3.z, acc[JA+3].y - v3.w); \
        }
        #define DO_D(DD) { \
            const float4* rb = bbase + (DD) * SLICE_F4; \
            const uint4* tm = (const uint4*) \
                (g_tmap + (size_t)((d0 + (DD)) * IND + i0 + il) * BATCHN + b0 + bg * 32); \
            uint4 ta = tm[0], tb = tm[1]; \
            STEP4(ta.x, zq0, 0)  STEP4(ta.y, zq1, 4) \
            STEP4(ta.z, zq2, 8)  STEP4(ta.w, zq3, 12) \
            STEP4(tb.x, zq4, 16) STEP4(tb.y, zq5, 20) \
            STEP4(tb.z, zq6, 24) STEP4(tb.w, zq7, 28) \
        }
        DO_D(0)
        if (nd == 2) DO_D(1)
        #undef DO_D
        #undef STEP4

        __syncwarp();                                          // all lanes' reads done
        if ((tid & 31) == 0) mbar_arrive((s & 1) ? eb1 : eb0); // warp consumed buffer s

        if (tid == 0 && s + 2 < NS) {
            mbar_wait((s & 1) ? eb1 : eb0, par);   // all 16 warps consumed buffer s
            stage(s + 2, (s & 1) ? rb1 : rb0, (s & 1) ? fb1 : fb0);
        }
    }

    int h0 = (hc * 16 + hp) * 2;
    float* outp = g_Hp + (size_t)ic * BATCHN * HIDN;
    #pragma unroll
    for (int j = 0; j < 32; j++) {
        int b = b0 + bg * 32 + j;
        *(float2*)&outp[(size_t)b * HIDN + h0] = acc[j];
    }
}

// ---------------- 4. MLP head ----------------
__device__ __forceinline__ float gelu_exact(float y) {
    return 0.5f * y * (1.0f + erff(y * 0.70710678118654752440f));
}

// act==0: src = g_Hp, sum NIC partials. act==1: BN(prev params)+GELU on src.
__global__ void __launch_bounds__(256) k_gemm(const float* __restrict__ W,
                                              const float* __restrict__ bias,
                                              const float* __restrict__ src,
                                              float* __restrict__ dst,
                                              int act) {
    __shared__ float Hs[16 * HIDN];
    int b0 = blockIdx.x * 16;
    int tid = threadIdx.x;
    for (int idx = tid; idx < 16 * HIDN; idx += 256) {
        size_t off = (size_t)b0 * HIDN + idx;
        float v;
        if (act) {
            v = src[off];
            float2 p = g_bnp[idx & (HIDN - 1)];
            v = gelu_exact(fmaf(v, p.x, p.y));
        } else {
            v = 0.f;
            #pragma unroll
            for (int p = 0; p < NIC; p++)
                v += src[(size_t)p * BATCHN * HIDN + off];
        }
        Hs[idx] = v;
    }
    __syncthreads();

    float acc[16];
    #pragma unroll
    for (int b = 0; b < 16; b++) acc[b] = 0.f;
    int hxc = tid;
    for (int k4 = 0; k4 < HIDN / 4; k4++) {
        float w0 = W[(4 * k4 + 0) * HIDN + hxc];
        float w1 = W[(4 * k4 + 1) * HIDN + hxc];
        float w2 = W[(4 * k4 + 2) * HIDN + hxc];
        float w3 = W[(4 * k4 + 3) * HIDN + hxc];
        #pragma unroll
        for (int b = 0; b < 16; b++) {
            float4 hv = *(const float4*)&Hs[b * HIDN + 4 * k4];
            acc[b] = fmaf(hv.x, w0, fmaf(hv.y, w1, fmaf(hv.z, w2, fmaf(hv.w, w3, acc[b]))));
        }
    }
    float bsv = bias[hxc];
    double s1 = 0.0, s2 = 0.0;
    #pragma unroll
    for (int b = 0; b < 16; b++) {
        float y = acc[b] + bsv;
        dst[(size_t)(b0 + b) * HIDN + hxc] = y;
        s1 += (double)y;
        s2 += (double)y * (double)y;
    }
    atomicAdd(&g_sum[hxc], s1);
    atomicAdd(&g_sumsq[hxc], s2);
}

__global__ void k_bnfin(const float* __restrict__ gamma, const float* __restrict__ beta) {
    int h = threadIdx.x;
    double mean = g_sum[h] / (double)BATCHN;
    double var  = g_sumsq[h] / (double)BATCHN - mean * mean;
    float scale = gamma[h] * rsqrtf((float)var + 1e-5f);
    float shift = beta[h] - (float)mean * scale;
    g_bnp[h] = make_float2(scale, shift);
    g_sum[h] = 0.0; g_sumsq[h] = 0.0;
}

__global__ void k_final(const float* __restrict__ Wout, const float* __restrict__ bout,
                        float* __restrict__ out) {
    int b = blockIdx.x * 8 + (threadIdx.x >> 5);
    int lane = threadIdx.x & 31;
    const float* hr = g_Hb + (size_t)b * HIDN;
    float s = 0.f;
    #pragma unroll
    for (int k = lane; k < HIDN; k += 32) {
        float2 p = g_bnp[k];
        float y = gelu_exact(fmaf(hr[k], p.x, p.y));
        s = fmaf(y, Wout[k], s);
    }
    #pragma unroll
    for (int o = 16; o > 0; o >>= 1) s += __shfl_down_sync(0xffffffffu, s, o);
    if (lane == 0) out[b] = s + bout[0];
}

// ---------------- launch ----------------
extern "C" void kernel_launch(void* const* d_in, const int* in_sizes, int n_in,
                              void* d_out, int out_size) {
    const float* x     = (const float*)d_in[0];
    const float* grids = (const float*)d_in[1];
    const float* fs    = (const float*)d_in[2];
    const float* ds    = (const float*)d_in[3];
    const float* mlpW  = (const float*)d_in[4];
    const float* mlpb  = (const float*)d_in[5];
    const float* gamma = (const float*)d_in[6];
    const float* beta  = (const float*)d_in[7];
    const float* Wout  = (const float*)d_in[8];
    const float* bout  = (const float*)d_in[9];
    float* out = (float*)d_out;

    float* Ha; float* Hb; float* Hp;
    cudaGetSymbolAddress((void**)&Ha, g_Ha);
    cudaGetSymbolAddress((void**)&Hb, g_Hb);
    cudaGetSymbolAddress((void**)&Hp, g_Hp);

    cudaFuncSetAttribute(k_main, cudaFuncAttributeMaxDynamicSharedMemorySize, SMEM_MAIN);

    k_prep1<<<IND, 256>>>(x);
    k_prep2<<<DDEPTH * IND, 128>>>(grids, fs, ds);
    k_main<<<128, MAIN_TPB, SMEM_MAIN>>>();

    k_gemm<<<BATCHN / 16, 256>>>(mlpW + 0 * HIDN * HIDN, mlpb + 0 * HIDN, Hp, Hb, 0);
    k_bnfin<<<1, HIDN>>>(gamma + 0 * HIDN, beta + 0 * HIDN);
    k_gemm<<<BATCHN / 16, 256>>>(mlpW + 1 * HIDN * HIDN, mlpb + 1 * HIDN, Hb, Ha, 1);
    k_bnfin<<<1, HIDN>>>(gamma + 1 * HIDN, beta + 1 * HIDN);
    k_gemm<<<BATCHN / 16, 256>>>(mlpW + 2 * HIDN * HIDN, mlpb + 2 * HIDN, Ha, Hb, 1);
    k_bnfin<<<1, HIDN>>>(gamma + 2 * HIDN, beta + 2 * HIDN);
    k_final<<<BATCHN / 8, 256>>>(Wout, bout, out);
}